// round 10
// baseline (speedup 1.0000x reference)
#include <cuda_runtime.h>
#include <cuda_bf16.h>
#include <cstdint>

// Problem shape (fixed for this registry entry)
#define B     8
#define T     200
#define U1    101        // U+1
#define V     1024
#define UD    104        // padded u-stride in diagonal-major layout (26 x 16B rows)
#define ND    300        // number of diagonals (T + U1 - 1)
#define PADR  16         // pad rows after the last batch (prefetch overrun; stay 0 = neutral-ish)
#define R4    (UD / 4)   // 26 uint4 per diagonal row
#define BATCH_ELEMS (ND * UD)   // 31200
#define LN2   0.6931471805599453f

// Diagonal-major packed scores: g_sc[b][d][u] = bf16x2( Bl, Lc ) where
//   Bl = exp(blank[t-1,u])  (neutral 1.0 if t<1 or cell invalid)
//   Lc = exp(lab  [t,  u])  (neutral 0.0 if u<1 or cell invalid),  t = d-u
__device__ __align__(16) __nv_bfloat162 g_sc[(B * ND + PADR) * UD];

// Producer->consumer element counters (release/acquire), per batch.
// Reset to 0 by the dp consumer at the end of every run (graph-replay safe).
__device__ int   g_cnt[B];
__device__ float g_part[B];    // per-batch ln(alpha) partials
__device__ int   g_done;       // last-arriver counter, reset by last CTA

// ---------------------------------------------------------------------------
// Kernel 1: gather + exponentiate the 2 useful channels of the 662MB logits
// tensor into the diagonal-major bf16x2 table. Signals per-batch progress via
// fence + atomicAdd so the PDL-overlapped dp kernel can consume early.
// ---------------------------------------------------------------------------
__global__ void gather_kernel(const float* __restrict__ logits,
                              const int* __restrict__ labels) {
    // Allow the dependent dp kernel to launch immediately (PDL trigger).
    asm volatile("griddepcontrol.launch_dependents;");

    int idx = blockIdx.x * 256 + threadIdx.x;      // grid covers exactly B*ND*UD

    int u = idx % UD;
    int d = (idx / UD) % ND;
    int b = idx / (UD * ND);
    int t = d - u;

    float bl = 1.0f, lc = 0.0f;                    // neutral: a' = a*1 + left*0
    if (u < U1 && t >= 0 && t < T) {
        if (t >= 1)
            bl = __expf(logits[((long)(b * T + (t - 1)) * U1 + u) * V]);
        if (u >= 1) {
            int lab = labels[b * (U1 - 1) + (u - 1)];
            lc = __expf(logits[((long)(b * T + t) * U1 + (u - 1)) * V + lab]);
        }
    }
    g_sc[idx] = __floats2bfloat162_rn(bl, lc);

    // Release our stores, then publish element counts (<=2 batches per CTA).
    __threadfence();
    __syncthreads();
    int base = blockIdx.x * 256;
    int b0 = base / BATCH_ELEMS;
    int b1 = (base + 255) / BATCH_ELEMS;
    int n0 = (b1 == b0) ? 256 : ((b0 + 1) * BATCH_ELEMS - base);
    if (threadIdx.x == 0)
        atomicAdd(&g_cnt[b0], n0);
    else if (threadIdx.x == 1 && b1 != b0)
        atomicAdd(&g_cnt[b1], 256 - n0);
}

// ---------------------------------------------------------------------------
// Kernel 2: one 32-thread CTA per batch (launched with PDL so it overlaps the
// gather; spins on the per-batch counter with acquire semantics). Linear-
// domain wavefront:  A[t,u] = A[t-1,u]*Bl + A[t,u-1]*Lc
// lane L owns u = 4L..4L+3; lefts are registers, 1 shfl/diag.
// Scores read straight from L2 (hot: written moments ago, same stream) via
// LDG.128 into two explicit 16-row register blocks, double-buffered.
// SHFL HOISTED OFF THE CRITICAL PATH: a3_new (independent of l0) is computed
// first, the next diagonal's shfl issues immediately, then a0..a2 use the
// previous l0 -> shfl latency fully overlapped.
// Exact power-of-2 renorm (redux.max) every 16 diagonals; l0 rescaled too.
// Final block snapshots state at step capRem, so overrun steps are harmless.
// ---------------------------------------------------------------------------
struct DPState { float a0, a1, a2, a3, l0; };

__device__ __forceinline__ float2 bf2_to_f2(uint32_t x) {
    float2 r;
    r.x = __int_as_float((int)(x << 16));          // low bf16  (Bl) -> f32 exact
    r.y = __int_as_float((int)(x & 0xFFFF0000u));  // high bf16 (Lc) -> f32 exact
    return r;
}

__device__ __forceinline__ void dp_step_v(DPState& s, uint4 cur, int lsrc) {
    float2 f3 = bf2_to_f2(cur.w);
    float a3n = fmaf(s.a3, f3.x, s.a2 * f3.y);     // needs no l0 -> compute 1st
    float l0n = __shfl_sync(0xffffffffu, a3n, lsrc);   // next diag's left, early
    float2 f0 = bf2_to_f2(cur.x);
    float2 f1 = bf2_to_f2(cur.y);
    float2 f2 = bf2_to_f2(cur.z);
    float a0n = fmaf(s.a0, f0.x, s.l0 * f0.y);     // Lc(u=0)=0 kills garbage l0
    float a1n = fmaf(s.a1, f1.x, s.a0 * f1.y);
    float a2n = fmaf(s.a2, f2.x, s.a1 * f2.y);
    s.a0 = a0n; s.a1 = a1n; s.a2 = a2n; s.a3 = a3n; s.l0 = l0n;
}

__device__ __forceinline__ void renorm(DPState& s, int& S) {
    float mx = fmaxf(fmaxf(s.a0, s.a1), fmaxf(s.a2, s.a3));
    // a >= 0 always -> unsigned bit-pattern order == float order
    unsigned mxi = __reduce_max_sync(0xffffffffu, (unsigned)__float_as_int(mx));
    int e = (int)(mxi >> 23) - 127;
    float sc = __int_as_float((127 - e) << 23);    // 2^-e, exact
    s.a0 *= sc; s.a1 *= sc; s.a2 *= sc; s.a3 *= sc;
    s.l0 *= sc;                                    // l0 crosses renorm boundary
    S += e;
}

__global__ void __launch_bounds__(32, 1)
dp_kernel(const int* __restrict__ loglen,
          const int* __restrict__ lablen,
          float* __restrict__ out) {
    const int b    = blockIdx.x;
    const int lane = threadIdx.x;
    const int lsrc = (lane + 31) & 31;

    // Wait for this batch's scores (acquire pairs with producers' fence+add)
    {
        int v;
        do {
            asm volatile("ld.acquire.gpu.global.s32 %0, [%1];"
                         : "=r"(v) : "l"(&g_cnt[b]));
        } while (v != BATCH_ELEMS);
    }

    const int Tb     = loglen[b];
    const int Lb     = lablen[b];
    const int nSteps = Tb + Lb;                    // diags 0..capD inclusive
    const int capD   = nSteps - 1;
    const int blkTot = (nSteps + 15) >> 4;
    const int nFull  = blkTot - 1;
    const int capRem = capD - nFull * 16;          // 0..15, snapshot step

    // lane's 16B slice of diagonal row r lives at gp[r * R4]
    const uint4* gp = reinterpret_cast<const uint4*>(g_sc)
                      + (size_t)(b * ND) * R4 + lane;

    DPState s;
    s.a0 = (lane == 0) ? 1.0f : 0.0f;              // A[.,u=0] seed (exp(0)=1)
    s.a1 = 0.0f; s.a2 = 0.0f; s.a3 = 0.0f;
    s.l0 = 0.0f;                                   // left of prev diag = seed 0
    int S = 0;
    float c0 = 0.0f, c1 = 0.0f, c2 = 0.0f, c3 = 0.0f;

    uint4 bufA[16], bufB[16];

    auto pref = [&](uint4 (&buf)[16], int blkIdx) {
        const uint4* q = gp + blkIdx * 16 * R4;
        #pragma unroll
        for (int k = 0; k < 16; ++k)
            buf[k] = q[k * R4];                    // 16 batched LDG.128 (L2 hot)
    };
    auto comp = [&](uint4 (&buf)[16]) {
        #pragma unroll
        for (int k = 0; k < 16; ++k)
            dp_step_v(s, buf[k], lsrc);
    };
    auto compLast = [&](uint4 (&buf)[16]) {
        #pragma unroll
        for (int k = 0; k < 16; ++k) {
            dp_step_v(s, buf[k], lsrc);
            if (k == capRem) { c0 = s.a0; c1 = s.a1; c2 = s.a2; c3 = s.a3; }
        }
    };

    pref(bufA, 0);
    int blk = 0;
    #pragma unroll 1
    while (blk + 2 <= nFull) {
        pref(bufB, blk + 1); renorm(s, S); comp(bufA);
        pref(bufA, blk + 2); renorm(s, S); comp(bufB);
        blk += 2;
    }
    if (blk == nFull) {                            // nFull even: last in A
        renorm(s, S); compLast(bufA);
    } else {                                       // blk == nFull-1: last in B
        pref(bufB, blk + 1); renorm(s, S); comp(bufA);
        renorm(s, S); compLast(bufB);
    }

    // Reset this batch's counter for the next run (no same-run readers left).
    if (lane == 0) g_cnt[b] = 0;

    // Publish per-batch partial; last CTA reduces and writes the scalar out.
    if (lane == (Lb >> 2)) {
        int ck = Lb & 3;
        float cap = (ck == 0) ? c0 : (ck == 1) ? c1 : (ck == 2) ? c2 : c3;
        g_part[b] = (log2f(cap) + (float)S) * LN2;     // ln(alpha_capture)
    }
    __threadfence();
    __syncwarp();
    if (lane == 0) {
        int old = atomicAdd(&g_done, 1);
        if (old == B - 1) {
            __threadfence();
            float sum = 0.0f;
            #pragma unroll
            for (int i = 0; i < B; ++i) sum += g_part[i];
            out[0] = -sum * (1.0f / B);            // mean loss
            g_done = 0;                            // reset for next run
        }
    }
}

// ---------------------------------------------------------------------------
extern "C" void kernel_launch(void* const* d_in, const int* in_sizes, int n_in,
                              void* d_out, int out_size) {
    const float* logits = (const float*)d_in[0];
    const int*   labels = (const int*)d_in[1];
    const int*   loglen = (const int*)d_in[2];
    const int*   lablen = (const int*)d_in[3];
    float* out = (float*)d_out;

    gather_kernel<<<(B * BATCH_ELEMS) / 256, 256>>>(logits, labels);  // 975 CTAs

    // dp launched with Programmatic Dependent Launch: it starts while gather
    // is still running and synchronizes via the g_cnt flags.
    cudaLaunchConfig_t cfg = {};
    cfg.gridDim        = {B, 1, 1};
    cfg.blockDim       = {32, 1, 1};
    cfg.dynamicSmemBytes = 0;
    cfg.stream         = 0;
    cudaLaunchAttribute at[1];
    at[0].id = cudaLaunchAttributeProgrammaticStreamSerialization;
    at[0].val.programmaticStreamSerializationAllowed = 1;
    cfg.attrs    = at;
    cfg.numAttrs = 1;
    cudaLaunchKernelEx(&cfg, dp_kernel, loglen, lablen, out);
}

// round 11
// speedup vs baseline: 1.1630x; 1.1630x over previous
#include <cuda_runtime.h>
#include <cuda_bf16.h>
#include <cstdint>

// Problem shape (fixed for this registry entry)
#define B     8
#define T     200
#define U1    101        // U+1
#define V     1024
#define UD    104        // padded cells per diagonal row
#define ND    300        // single-step diagonals (T + U1 - 1)
#define NPR   168        // padded pair-rows per batch (21 blocks of 8)
#define NPREAL 150       // real pair rows (ceil(ND/2))
#define CHROWS 42        // pair rows per staging chunk
#define NCH   4          // staging chunks (4*42 = 168)
#define LN2   0.6931471805599453f

// Pair-step coefficient planes (SoA for conflict-free LDS):
//   A-plane: uint32 = bf16x2 (c0, c1) per cell
//   B-plane: bf16   = c2 per cell
// a_{d+2}(u) = c0*a(u) + c1*a(u-1) + c2*a(u-2)
__device__ __align__(16) uint32_t      g_pA[B * NPR * UD];
__device__ __align__(16) __nv_bfloat16 g_pB[B * NPR * UD];

__device__ __forceinline__ uint32_t smem_u32(const void* p) {
    uint32_t a;
    asm("{ .reg .u64 t; cvta.to.shared.u64 t, %1; cvt.u32.u64 %0, t; }"
        : "=r"(a) : "l"(p));
    return a;
}

// ---------------------------------------------------------------------------
// Kernel 1: gather + compose. Single-step scores (neutral-padded, proven in
// R5..R9):  Bl(r,u)=exp(blank[t-1,u]) (1 if invalid/t<1), Lc(r,u)=exp(lab)
// (0 if invalid/u<1), t=r-u; r<0 = identity row (odd-length batches start
// with an identity half so every batch runs ceil(nSteps/2) uniform pairs).
// Pair p composes single rows (2p-off, 2p-off+1), off = nSteps&1.
// Also zero-inits the scalar output.
// ---------------------------------------------------------------------------
__device__ __forceinline__ float2 get_BL(const float* __restrict__ logits,
                                         const int* __restrict__ labels,
                                         int b, int r, int u) {
    if (r < 0 || u < 0 || u >= U1) return make_float2(1.0f, 0.0f);
    int t = r - u;
    if (t < 0 || t >= T) return make_float2(1.0f, 0.0f);
    float Bl = 1.0f, Lc = 0.0f;
    if (t >= 1)
        Bl = __expf(logits[((long)(b * T + (t - 1)) * U1 + u) * V]);
    if (u >= 1)
        Lc = __expf(logits[((long)(b * T + t) * U1 + (u - 1)) * V
                           + labels[b * (U1 - 1) + (u - 1)]]);
    return make_float2(Bl, Lc);
}

__global__ void gather_kernel(const float* __restrict__ logits,
                              const int* __restrict__ labels,
                              const int* __restrict__ loglen,
                              const int* __restrict__ lablen,
                              float* __restrict__ out) {
    int idx = blockIdx.x * 256 + threadIdx.x;
    if (idx == 0) out[0] = 0.0f;
    if (idx >= B * NPR * UD) return;

    int u = idx % UD;
    int p = (idx / UD) % NPR;
    int b = idx / (UD * NPR);

    float c0 = 0.0f, c1 = 0.0f, c2 = 0.0f;         // pad rows: dead map
    if (p < NPREAL) {
        int off = (loglen[b] + lablen[b]) & 1;
        int r1 = 2 * p - off;
        float2 s1  = get_BL(logits, labels, b, r1,     u);
        float2 s1m = get_BL(logits, labels, b, r1,     u - 1);
        float2 s2  = get_BL(logits, labels, b, r1 + 1, u);
        c0 = s2.x * s1.x;                          // B2*B1
        c1 = fmaf(s2.x, s1.y, s2.y * s1m.x);       // B2*L1 + L2*B1(u-1)
        c2 = s2.y * s1m.y;                         // L2*L1(u-1)
    }
    __nv_bfloat162 p01 = __floats2bfloat162_rn(c0, c1);
    g_pA[idx] = *reinterpret_cast<uint32_t*>(&p01);
    g_pB[idx] = __float2bfloat16_rn(c2);
}

// ---------------------------------------------------------------------------
// Kernel 2: one 32-thread CTA per batch. Chunked bulk-copy staging (4 chunks,
// 4 TRYWAITs total, overlaps compute). Pair-step wavefront: every step reads
// ONLY old state -> zero intra-step serial chain; both shfls issue at step
// top. lane L owns u = 4L..4L+3. Exact power-of-2 renorm (redux.max) every
// 8 pair-steps (=16 diagonals, proven cadence). Final block snapshots state
// at pair capRem; later (zeroed-pad) steps are dead maps.
// ---------------------------------------------------------------------------
struct DPState { float a0, a1, a2, a3; };
struct PairBuf { uint4 ab[8]; uint2 c2[8]; };

__device__ __forceinline__ float bflo(uint32_t x) {
    return __int_as_float((int)(x << 16));
}
__device__ __forceinline__ float bfhi(uint32_t x) {
    return __int_as_float((int)(x & 0xFFFF0000u));
}

__device__ __forceinline__ void pair_step(DPState& s, uint4 ab, uint2 cc,
                                          int lsrc) {
    float p3 = __shfl_sync(0xffffffffu, s.a3, lsrc);   // a(u-1) for cell 0
    float p2 = __shfl_sync(0xffffffffu, s.a2, lsrc);   // a(u-2) for cell 0
    float n0 = fmaf(bflo(ab.x), s.a0,
               fmaf(bfhi(ab.x), p3,   bflo(cc.x) * p2));
    float n1 = fmaf(bflo(ab.y), s.a1,
               fmaf(bfhi(ab.y), s.a0, bfhi(cc.x) * p3));
    float n2 = fmaf(bflo(ab.z), s.a2,
               fmaf(bfhi(ab.z), s.a1, bflo(cc.y) * s.a0));
    float n3 = fmaf(bflo(ab.w), s.a3,
               fmaf(bfhi(ab.w), s.a2, bfhi(cc.y) * s.a1));
    s.a0 = n0; s.a1 = n1; s.a2 = n2; s.a3 = n3;
}

__device__ __forceinline__ void renorm(DPState& s, int& S) {
    float mx = fmaxf(fmaxf(s.a0, s.a1), fmaxf(s.a2, s.a3));
    unsigned mxi = __reduce_max_sync(0xffffffffu, (unsigned)__float_as_int(mx));
    int e = (int)(mxi >> 23) - 127;
    float sc = __int_as_float((127 - e) << 23);        // 2^-e, exact
    s.a0 *= sc; s.a1 *= sc; s.a2 *= sc; s.a3 *= sc;
    S += e;
}

__global__ void __launch_bounds__(32, 1)
dp_kernel(const int* __restrict__ loglen,
          const int* __restrict__ lablen,
          float* __restrict__ out) {
    extern __shared__ __align__(16) char sm[];
    // layout: A-plane [NPR*UD] uint32, then B-plane [NPR*UD] bf16
    uint32_t* smA = reinterpret_cast<uint32_t*>(sm);
    __nv_bfloat16* smB = reinterpret_cast<__nv_bfloat16*>(sm + NPR * UD * 4);
    __shared__ __align__(8) unsigned long long mbars[NCH];

    const int b    = blockIdx.x;
    const int lane = threadIdx.x;
    const int lsrc = (lane + 31) & 31;

    if (lane == 0) {
        #pragma unroll
        for (int c = 0; c < NCH; ++c)
            asm volatile("mbarrier.init.shared.b64 [%0], %1;"
                         :: "r"(smem_u32(&mbars[c])), "r"(1) : "memory");
        asm volatile("fence.proxy.async.shared::cta;" ::: "memory");
        #pragma unroll 1
        for (int c = 0; c < NCH; ++c) {
            uint32_t txA = CHROWS * UD * 4u;       // 17472
            uint32_t txB = CHROWS * UD * 2u;       // 8736
            uint32_t mb  = smem_u32(&mbars[c]);
            asm volatile("mbarrier.arrive.expect_tx.shared.b64 _, [%0], %1;"
                         :: "r"(mb), "r"(txA + txB) : "memory");
            asm volatile(
                "cp.async.bulk.shared::cluster.global.mbarrier::complete_tx::bytes"
                " [%0], [%1], %2, [%3];"
                :: "r"(smem_u32(smA + c * CHROWS * UD)),
                   "l"(g_pA + (size_t)(b * NPR + c * CHROWS) * UD),
                   "r"(txA), "r"(mb) : "memory");
            asm volatile(
                "cp.async.bulk.shared::cluster.global.mbarrier::complete_tx::bytes"
                " [%0], [%1], %2, [%3];"
                :: "r"(smem_u32(smB + c * CHROWS * UD)),
                   "l"(g_pB + (size_t)(b * NPR + c * CHROWS) * UD),
                   "r"(txB), "r"(mb) : "memory");
        }
    }
    __syncwarp();

    int cw = 0;
    auto ensure = [&](int c) {                     // wait chunks 0..c
        while (cw <= c) {
            uint32_t mb = smem_u32(&mbars[cw]);
            uint32_t done = 0;
            while (!done)
                asm volatile(
                    "{\n\t.reg .pred p;\n\t"
                    "mbarrier.try_wait.parity.acquire.cta.shared::cta.b64 p, [%1], %2;\n\t"
                    "selp.b32 %0, 1, 0, p;\n\t}"
                    : "=r"(done) : "r"(mb), "r"(0u) : "memory");
            ++cw;
        }
    };

    const int Tb     = loglen[b];
    const int Lb     = lablen[b];
    const int nSteps = Tb + Lb;                    // single-step diagonals
    const int nPair  = (nSteps + 1) >> 1;          // uniform pair-steps
    const int blkTot = (nPair + 7) >> 3;           // 8-pair blocks
    const int nFull  = blkTot - 1;
    const int capRem = (nPair - 1) - nFull * 8;    // 0..7 snapshot step

    DPState s;
    s.a0 = (lane == 0) ? 1.0f : 0.0f;              // seed A = exp(alpha) at -inf row
    s.a1 = 0.0f; s.a2 = 0.0f; s.a3 = 0.0f;
    int S = 0;
    float c0 = 0.0f, c1 = 0.0f, c2 = 0.0f, c3 = 0.0f;

    // lane slices: A row r -> uint4 index r*26 + lane (stride 4 words, no conflict)
    //              B row r -> uint2 index r*26 + lane (stride 2 words, no conflict)
    const uint4* pa = reinterpret_cast<const uint4*>(smA) + lane;
    const uint2* pb = reinterpret_cast<const uint2*>(smB) + lane;

    PairBuf bufA, bufB;
    auto pref = [&](PairBuf& buf, int blk) {
        int base = blk * 8 * 26;
        #pragma unroll
        for (int k = 0; k < 8; ++k) {
            buf.ab[k] = pa[base + k * 26];
            buf.c2[k] = pb[base + k * 26];
        }
    };
    auto comp = [&](PairBuf& buf) {
        renorm(s, S);
        #pragma unroll
        for (int k = 0; k < 8; ++k)
            pair_step(s, buf.ab[k], buf.c2[k], lsrc);
    };
    auto compLast = [&](PairBuf& buf) {
        renorm(s, S);
        #pragma unroll
        for (int k = 0; k < 8; ++k) {
            pair_step(s, buf.ab[k], buf.c2[k], lsrc);
            if (k == capRem) { c0 = s.a0; c1 = s.a1; c2 = s.a2; c3 = s.a3; }
        }
    };
    auto cb = [](int blk) { return (8 * blk + 7) / CHROWS; };  // chunk of block

    ensure(cb(0));
    pref(bufA, 0);
    int blk = 0;
    #pragma unroll 1
    while (blk + 2 <= nFull) {
        ensure(cb(blk + 1)); pref(bufB, blk + 1); comp(bufA);
        ensure(cb(blk + 2)); pref(bufA, blk + 2); comp(bufB);
        blk += 2;
    }
    if (blk == nFull) {
        compLast(bufA);
    } else {
        ensure(cb(blk + 1)); pref(bufB, blk + 1); comp(bufA);
        compLast(bufB);
    }

    if (lane == (Lb >> 2)) {
        int ck = Lb & 3;
        float cap = (ck == 0) ? c0 : (ck == 1) ? c1 : (ck == 2) ? c2 : c3;
        float loss = -(log2f(cap) + (float)S) * LN2;   // back to nats
        atomicAdd(out, loss * (1.0f / B));             // mean over batch
    }
}

// ---------------------------------------------------------------------------
extern "C" void kernel_launch(void* const* d_in, const int* in_sizes, int n_in,
                              void* d_out, int out_size) {
    const float* logits = (const float*)d_in[0];
    const int*   labels = (const int*)d_in[1];
    const int*   loglen = (const int*)d_in[2];
    const int*   lablen = (const int*)d_in[3];
    float* out = (float*)d_out;

    const int total      = B * NPR * UD;           // 139776
    const int smem_bytes = NPR * UD * 4 + NPR * UD * 2;  // 104832 B

    cudaFuncSetAttribute(dp_kernel,
                         cudaFuncAttributeMaxDynamicSharedMemorySize,
                         smem_bytes);

    gather_kernel<<<(total + 255) / 256, 256>>>(logits, labels, loglen, lablen, out);
    dp_kernel<<<B, 32, smem_bytes>>>(loglen, lablen, out);
}